// round 10
// baseline (speedup 1.0000x reference)
#include <cuda_runtime.h>
#include <cstdint>
#include <math.h>

#define NB 2
#define NT 2048
#define NC 2048
#define NH 16
#define HD 128
#define NM (NB*NT)      /* 4096 rows */
#define N3C (3*NC)      /* 6144 */

// ---------------- scratch (device globals; no allocations allowed) ----------
__device__ float g_q[(size_t)NB*NH*NT*HD];
__device__ float g_k[(size_t)NB*NH*NT*HD];
__device__ float g_v[(size_t)NB*NH*NT*HD];
__device__ float g_y[(size_t)NM*NC];
__device__ float g_xr[(size_t)NM*NC];       // tf32-rounded x
__device__ float g_war[(size_t)N3C*NC];     // tf32-rounded w_att
__device__ float g_wpr[(size_t)NC*NC];      // tf32-rounded w_proj

// ---------------- helpers ----------------------------------------------------
__device__ __forceinline__ float to_tf32(float x) {
    float r;
    asm("cvt.rna.tf32.f32 %0, %1;" : "=f"(r) : "f"(x));
    return r;
}
__device__ __forceinline__ uint32_t smem_u32(const void* p) {
    uint32_t a;
    asm("{ .reg .u64 t; cvta.to.shared.u64 t, %1; cvt.u32.u64 %0, t; }"
        : "=r"(a) : "l"(p));
    return a;
}
__device__ __forceinline__ void cpasync16(uint32_t s, const void* g) {
    asm volatile("cp.async.cg.shared.global [%0], [%1], 16;" :: "r"(s), "l"(g));
}
#define CP_COMMIT()  asm volatile("cp.async.commit_group;" ::: "memory")
#define CP_WAIT1()   asm volatile("cp.async.wait_group 1;" ::: "memory")

__device__ __forceinline__ void mma_tf32(float* c, const uint32_t* a, const uint32_t* b) {
    asm volatile(
        "mma.sync.aligned.m16n8k8.row.col.f32.tf32.tf32.f32 "
        "{%0,%1,%2,%3}, {%4,%5,%6,%7}, {%8,%9}, {%0,%1,%2,%3};"
        : "+f"(c[0]), "+f"(c[1]), "+f"(c[2]), "+f"(c[3])
        : "r"(a[0]), "r"(a[1]), "r"(a[2]), "r"(a[3]), "r"(b[0]), "r"(b[1]));
}

// fast exp for x <= 0: FMA/ALU pipes only.
__device__ __forceinline__ float fexp(float x) {
    float t = fmaxf(x * 1.442695041f, -126.0f);
    float r = t + 12582912.0f;
    float i = r - 12582912.0f;
    float f = t - i;
    float p =              1.3333558e-3f;
    p = fmaf(p, f, 9.6181291e-3f);
    p = fmaf(p, f, 5.5504109e-2f);
    p = fmaf(p, f, 2.4022651e-1f);
    p = fmaf(p, f, 6.9314718e-1f);
    p = fmaf(p, f, 1.0f);
    int sb = (__float_as_int(r) << 23) + 0x3F800000;
    return p * __int_as_float(sb);
}

// ---------------- pre-round inputs to tf32 (RNA) ------------------------------
__global__ void round_kernel(const float* __restrict__ in, float* __restrict__ out, int n4)
{
    int i = blockIdx.x * blockDim.x + threadIdx.x;
    if (i < n4) {
        float4 v = ((const float4*)in)[i];
        v.x = to_tf32(v.x); v.y = to_tf32(v.y);
        v.z = to_tf32(v.z); v.w = to_tf32(v.w);
        ((float4*)out)[i] = v;
    }
}

// ---------------- tf32 tensor-core GEMM v3: out = A @ W^T + bias --------------
// CTA 256(M) x 128(N), 16 warps as 4m x 4n of 64x32 warp tiles (acc=64 regs).
// cp.async 3-stage pipeline, K-chunk 16, smem row stride 20 (conflict-free).
// MODE 0: A=g_xr, W=g_war -> scatter to g_q/g_k/g_v. MODE 1: A=g_y, W=g_wpr -> out.
#define ASTRIDE 20
#define A_ST_FL (256*ASTRIDE)                 /* 5120 */
#define B_ST_FL (128*ASTRIDE)                 /* 2560 */
#define ST_FL   (A_ST_FL + B_ST_FL)           /* 7680 floats = 30720 B */
#define NSTAGE  3
#define GEMM_SMEM (NSTAGE*ST_FL*4)            /* 92160 B */

template<int MODE>
__global__ __launch_bounds__(512, 1)
void mgemm3_kernel(const float* __restrict__ bias, float* __restrict__ out)
{
    extern __shared__ float sm2[];
    const float* A = (MODE == 1) ? (const float*)g_y : (const float*)g_xr;
    const float* W = (MODE == 1) ? (const float*)g_wpr : (const float*)g_war;
    const int K = NC;

    const int tid = threadIdx.x;
    const int lane = tid & 31, wid = tid >> 5;       // wid 0..15
    const int qr = lane >> 2, qc = lane & 3;
    const int wm = (wid >> 2) * 64;                  // 4 m-warps
    const int wn = (wid & 3) * 32;                   // 4 n-warps
    const int m0 = blockIdx.y * 256;
    const int n0 = blockIdx.x * 128;

    // staging mapping: thread -> row tid>>2 (0..127, +128 for A), chunk (tid&3)
    const int srow = tid >> 2;
    const int sch  = (tid & 3) * 4;
    const float* Ag = A + (size_t)(m0 + srow) * K + sch;
    const float* Wg = W + (size_t)(n0 + srow) * K + sch;
    const uint32_t sm_base = smem_u32(sm2);
    const uint32_t a_sm = sm_base + (uint32_t)(srow * ASTRIDE + sch) * 4;
    const uint32_t b_sm = a_sm + A_ST_FL * 4;

    float acc[4][4][4];
#pragma unroll
    for (int i = 0; i < 4; i++)
#pragma unroll
        for (int j = 0; j < 4; j++)
#pragma unroll
            for (int v = 0; v < 4; v++) acc[i][j][v] = 0.f;

    const int NCHU = K / 16;   // 128

    // prologue: stages 0, 1
#pragma unroll
    for (int s = 0; s < 2; s++) {
        const int k0 = s * 16;
        const uint32_t so = (uint32_t)(s * ST_FL) * 4;
        cpasync16(a_sm + so, Ag + k0);
        cpasync16(a_sm + so + (uint32_t)(128 * ASTRIDE) * 4, Ag + (size_t)128 * K + k0);
        cpasync16(b_sm + so, Wg + k0);
        CP_COMMIT();
    }

    int stage = 0;
    int nstage = 2;
#pragma unroll 1
    for (int c = 0; c < NCHU; ++c) {
        CP_WAIT1();
        __syncthreads();

        if (c + 2 < NCHU) {
            const int k0 = (c + 2) * 16;
            const uint32_t so = (uint32_t)(nstage * ST_FL) * 4;
            cpasync16(a_sm + so, Ag + k0);
            cpasync16(a_sm + so + (uint32_t)(128 * ASTRIDE) * 4, Ag + (size_t)128 * K + k0);
            cpasync16(b_sm + so, Wg + k0);
        }
        CP_COMMIT();

        const float* as = sm2 + stage * ST_FL;
        const float* bs = as + A_ST_FL;
#pragma unroll
        for (int kk = 0; kk < 16; kk += 8) {
            uint32_t af[4][4];
#pragma unroll
            for (int i = 0; i < 4; i++) {
                const float* ap = as + (wm + i * 16 + qr) * ASTRIDE + kk + qc;
                af[i][0] = __float_as_uint(ap[0]);
                af[i][1] = __float_as_uint(ap[8 * ASTRIDE]);
                af[i][2] = __float_as_uint(ap[4]);
                af[i][3] = __float_as_uint(ap[8 * ASTRIDE + 4]);
            }
#pragma unroll
            for (int j = 0; j < 4; j++) {
                uint32_t bf[2];
                const float* bp = bs + (wn + j * 8 + qr) * ASTRIDE + kk + qc;
                bf[0] = __float_as_uint(bp[0]);
                bf[1] = __float_as_uint(bp[4]);
#pragma unroll
                for (int i = 0; i < 4; i++)
                    mma_tf32(acc[i][j], af[i], bf);
            }
        }

        stage = (stage == NSTAGE - 1) ? 0 : stage + 1;
        nstage = (nstage == NSTAGE - 1) ? 0 : nstage + 1;
    }

    // ---- epilogue: add bias, store ----
#pragma unroll
    for (int i = 0; i < 4; i++) {
#pragma unroll
        for (int j = 0; j < 4; j++) {
            const int ncol = n0 + wn + j * 8 + (qc << 1);
            const float b0 = bias[ncol], b1 = bias[ncol + 1];
            const int r0 = m0 + wm + i * 16 + qr;
            float2 lo = make_float2(acc[i][j][0] + b0, acc[i][j][1] + b1);
            float2 hi = make_float2(acc[i][j][2] + b0, acc[i][j][3] + b1);
            if (MODE == 0) {
                const int which = ncol >> 11;
                const int h = (ncol >> 7) & 15;
                const int d = ncol & 127;
                float* dst = (which == 0) ? g_q : ((which == 1) ? g_k : g_v);
                if (which == 2) {   // v feeds tf32 MMA directly: pre-round
                    lo.x = to_tf32(lo.x); lo.y = to_tf32(lo.y);
                    hi.x = to_tf32(hi.x); hi.y = to_tf32(hi.y);
                }
                int bb = r0 >> 11, t0 = r0 & 2047;
                *(float2*)&dst[(((size_t)bb * NH + h) * NT + t0) * HD + d] = lo;
                const int r1 = r0 + 8;
                bb = r1 >> 11; t0 = r1 & 2047;
                *(float2*)&dst[(((size_t)bb * NH + h) * NT + t0) * HD + d] = hi;
            } else {
                *(float2*)&out[(size_t)r0 * NC + ncol] = lo;
                *(float2*)&out[(size_t)(r0 + 8) * NC + ncol] = hi;
            }
        }
    }
}

// ---------------- RoPE (in-place; q pre-scaled by 1/sqrt(D); tf32-rounded) ---
__global__ void rope_kernel()
{
    int idx = blockIdx.x * blockDim.x + threadIdx.x;
    int pair  = idx & 63;
    int row   = (idx >> 6) & (NB*NH*NT - 1);
    int which = idx >> 22;
    float* buf = which ? g_k : g_q;
    int t = row & (NT - 1);
    float theta = powf(10000.0f, -(float)(2 * pair) * (1.0f / 128.0f));
    float fr = (float)t * theta;
    float s, c;
    sincosf(fr, &s, &c);
    size_t off = (size_t)row * 64 + pair;
    float2 v = ((float2*)buf)[off];
    float ox = v.x * c - v.y * s;
    float oy = v.x * s + v.y * c;
    if (which == 0) {
        const float scale = 0.08838834764831845f;
        ox *= scale; oy *= scale;
    }
    float2 o;
    o.x = to_tf32(ox);
    o.y = to_tf32(oy);
    ((float2*)buf)[off] = o;
}

// ---------------- Flash attention (tf32 mma, causal) -------------------------
#define AQS 132
#define AKS 132
#define AVS 136
#define APS 76
#define OFF_Q 0
#define OFF_K (128*AQS)
#define OFF_V (OFF_K + 2*64*AKS)
#define OFF_P (OFF_V + 64*AVS)
#define ATTN_FLOATS (OFF_P + 128*APS)

__global__ __launch_bounds__(256)
void attn_kernel()
{
    extern __shared__ float sm[];
    const uint32_t sb = smem_u32(sm);
    const int tid = threadIdx.x;
    const int lane = tid & 31, w = tid >> 5;
    const int qrow = lane >> 2, qcol = lane & 3;
    const int bh = blockIdx.y;
    const int qt = (gridDim.x - 1) - blockIdx.x;
    const int q0 = qt * 128;
    const float* Qg = g_q + (size_t)bh * NT * HD + (size_t)q0 * HD;
    const float* Kg = g_k + (size_t)bh * NT * HD;
    const float* Vg = g_v + (size_t)bh * NT * HD;

    for (int c = tid; c < 128 * 32; c += 256) {
        int row = c >> 5, ch = (c & 31) * 4;
        asm volatile("cp.async.ca.shared.global [%0], [%1], 16;"
            :: "r"(sb + (uint32_t)(OFF_Q + row * AQS + ch) * 4),
               "l"(Qg + (size_t)row * HD + ch));
    }
    for (int c = tid; c < 64 * 32; c += 256) {
        int row = c >> 5, ch = (c & 31) * 4;
        asm volatile("cp.async.ca.shared.global [%0], [%1], 16;"
            :: "r"(sb + (uint32_t)(OFF_K + row * AKS + ch) * 4),
               "l"(Kg + (size_t)row * HD + ch));
    }
    CP_COMMIT();
    for (int c = tid; c < 64 * 32; c += 256) {
        int row = c >> 5, ch = (c & 31) * 4;
        asm volatile("cp.async.ca.shared.global [%0], [%1], 16;"
            :: "r"(sb + (uint32_t)(OFF_V + row * AVS + ch) * 4),
               "l"(Vg + (size_t)row * HD + ch));
    }
    CP_COMMIT();

    float o[16][4];
#pragma unroll
    for (int jd = 0; jd < 16; jd++)
#pragma unroll
        for (int v = 0; v < 4; v++) o[jd][v] = 0.f;
    float m0 = -1e30f, m1 = -1e30f, l0 = 0.f, l1 = 0.f;
    const int r_lo = 16 * w + qrow;

    const float* qs = sm + OFF_Q + (16 * w) * AQS;
    float* psw = sm + OFF_P + (16 * w) * APS;

    const int nkt = (qt + 1) * 2;
    for (int kt = 0; kt < nkt; ++kt) {
        const int k0 = kt * 64;
        const int kb = kt & 1;

        CP_WAIT1();
        __syncthreads();

        if (kt + 1 < nkt) {
            const float* Kn = Kg + (size_t)(k0 + 64) * HD;
            uint32_t kdst = sb + (uint32_t)(OFF_K + (kb ^ 1) * 64 * AKS) * 4;
            for (int c = tid; c < 64 * 32; c += 256) {
                int row = c >> 5, ch = (c & 31) * 4;
                asm volatile("cp.async.ca.shared.global [%0], [%1], 16;"
                    :: "r"(kdst + (uint32_t)(row * AKS + ch) * 4),
                       "l"(Kn + (size_t)row * HD + ch));
            }
        }
        CP_COMMIT();

        float s[8][4];
#pragma unroll
        for (int j = 0; j < 8; j++)
#pragma unroll
            for (int v = 0; v < 4; v++) s[j][v] = 0.f;

        const float* ks = sm + OFF_K + kb * 64 * AKS;
#pragma unroll
        for (int kk = 0; kk < 16; ++kk) {
            const int kc = kk * 8;
            uint32_t a[4];
            a[0] = __float_as_uint(qs[qrow * AQS + kc + qcol]);
            a[1] = __float_as_uint(qs[(qrow + 8) * AQS + kc + qcol]);
            a[2] = __float_as_uint(qs[qrow * AQS + kc + qcol + 4]);
            a[3] = __float_as_uint(qs[(qrow + 8) * AQS + kc + qcol + 4]);
#pragma unroll
            for (int j = 0; j < 8; j++) {
                uint32_t b[2];
                b[0] = __float_as_uint(ks[(8 * j + qrow) * AKS + kc + qcol]);
                b[1] = __float_as_uint(ks[(8 * j + qrow) * AKS + kc + qcol + 4]);
                mma_tf32(s[j], a, b);
            }
        }

        if (k0 + 64 > q0) {
            const int row0 = q0 + r_lo;
#pragma unroll
            for (int j = 0; j < 8; j++) {
                const int key = k0 + 8 * j + 2 * qcol;
                if (key     > row0)     s[j][0] = -1e30f;
                if (key + 1 > row0)     s[j][1] = -1e30f;
                if (key     > row0 + 8) s[j][2] = -1e30f;
                if (key + 1 > row0 + 8) s[j][3] = -1e30f;
            }
        }

        float mx0 = -1e30f, mx1 = -1e30f;
#pragma unroll
        for (int j = 0; j < 8; j++) {
            mx0 = fmaxf(mx0, fmaxf(s[j][0], s[j][1]));
            mx1 = fmaxf(mx1, fmaxf(s[j][2], s[j][3]));
        }
        mx0 = fmaxf(mx0, __shfl_xor_sync(0xffffffffu, mx0, 1));
        mx0 = fmaxf(mx0, __shfl_xor_sync(0xffffffffu, mx0, 2));
        mx1 = fmaxf(mx1, __shfl_xor_sync(0xffffffffu, mx1, 1));
        mx1 = fmaxf(mx1, __shfl_xor_sync(0xffffffffu, mx1, 2));
        const float mn0 = fmaxf(m0, mx0), mn1 = fmaxf(m1, mx1);
        const float fac0 = fexp(m0 - mn0), fac1 = fexp(m1 - mn1);
        m0 = mn0; m1 = mn1;

        float sum0 = 0.f, sum1 = 0.f;
#pragma unroll
        for (int j = 0; j < 8; j++) {
            float p00 = fexp(s[j][0] - mn0);
            float p01 = fexp(s[j][1] - mn0);
            float p10 = fexp(s[j][2] - mn1);
            float p11 = fexp(s[j][3] - mn1);
            sum0 += p00 + p01;
            sum1 += p10 + p11;
            *(float2*)&psw[qrow * APS + 8 * j + 2 * qcol] =
                make_float2(to_tf32(p00), to_tf32(p01));
            *(float2*)&psw[(qrow + 8) * APS + 8 * j + 2 * qcol] =
                make_float2(to_tf32(p10), to_tf32(p11));
        }
        sum0 += __shfl_xor_sync(0xffffffffu, sum0, 1);
        sum0 += __shfl_xor_sync(0xffffffffu, sum0, 2);
        sum1 += __shfl_xor_sync(0xffffffffu, sum1, 1);
        sum1 += __shfl_xor_sync(0xffffffffu, sum1, 2);
        l0 = l0 * fac0 + sum0;
        l1 = l1 * fac1 + sum1;

#pragma unroll
        for (int jd = 0; jd < 16; jd++) {
            o[jd][0] *= fac0; o[jd][1] *= fac0;
            o[jd][2] *= fac1; o[jd][3] *= fac1;
        }
        __syncwarp();

        CP_WAIT1();
        __syncthreads();

        const float* vs = sm + OFF_V;
#pragma unroll
        for (int kk = 0; kk < 8; ++kk) {
            const int kc = kk * 8;
            uint32_t a[4];
            a[0] = __float_as_uint(psw[qrow * APS + kc + qcol]);
            a[1] = __float_as_uint(psw[(qrow + 8) * APS + kc + qcol]);
            a[2] = __float_as_uint(psw[qrow * APS + kc + qcol + 4]);
            a[3] = __float_as_uint(psw[(qrow + 8) * APS + kc + qcol + 4]);
#pragma unroll
            for (int jd = 0; jd < 16; jd++) {
                uint32_t b[2];
                b[0] = __float_as_uint(vs[(kc + qcol) * AVS + 8 * jd + qrow]);
                b[1] = __float_as_uint(vs[(kc + qcol + 4) * AVS + 8 * jd + qrow]);
                mma_tf32(o[jd], a, b);
            }
        }

        __syncthreads();

        if (kt + 1 < nkt) {
            const float* Vn = Vg + (size_t)(k0 + 64) * HD;
            for (int c = tid; c < 64 * 32; c += 256) {
                int row = c >> 5, ch = (c & 31) * 4;
                asm volatile("cp.async.ca.shared.global [%0], [%1], 16;"
                    :: "r"(sb + (uint32_t)(OFF_V + row * AVS + ch) * 4),
                       "l"(Vn + (size_t)row * HD + ch));
            }
            CP_COMMIT();
        }
    }

    // epilogue: O / l -> g_y [B,T,C], pre-rounded to tf32 for the proj GEMM
    const float il0 = 1.0f / l0, il1 = 1.0f / l1;
    const int bb = bh >> 4, h = bh & 15;
    const int t0g = q0 + r_lo;
    float* y0 = g_y + ((size_t)bb * NT + t0g) * NC + h * HD;
    float* y1 = g_y + ((size_t)bb * NT + t0g + 8) * NC + h * HD;
#pragma unroll
    for (int jd = 0; jd < 16; jd++) {
        const int d = 8 * jd + 2 * qcol;
        *(float2*)&y0[d] = make_float2(to_tf32(o[jd][0] * il0), to_tf32(o[jd][1] * il0));
        *(float2*)&y1[d] = make_float2(to_tf32(o[jd][2] * il1), to_tf32(o[jd][3] * il1));
    }
}

// ---------------- launch ------------------------------------------------------
extern "C" void kernel_launch(void* const* d_in, const int* in_sizes, int n_in,
                              void* d_out, int out_size)
{
    const float* x      = (const float*)d_in[0];
    const float* w_att  = (const float*)d_in[1];
    const float* b_att  = (const float*)d_in[2];
    const float* w_proj = (const float*)d_in[3];
    const float* b_proj = (const float*)d_in[4];
    float* out = (float*)d_out;

    cudaFuncSetAttribute(mgemm3_kernel<0>,
                         cudaFuncAttributeMaxDynamicSharedMemorySize, GEMM_SMEM);
    cudaFuncSetAttribute(mgemm3_kernel<1>,
                         cudaFuncAttributeMaxDynamicSharedMemorySize, GEMM_SMEM);
    const int attn_smem = ATTN_FLOATS * (int)sizeof(float);
    cudaFuncSetAttribute(attn_kernel,
                         cudaFuncAttributeMaxDynamicSharedMemorySize, attn_smem);

    // 0) pre-round inputs to tf32 (RNA) scratch copies
    float* d_xr;  cudaGetSymbolAddress((void**)&d_xr,  g_xr);
    float* d_war; cudaGetSymbolAddress((void**)&d_war, g_war);
    float* d_wpr; cudaGetSymbolAddress((void**)&d_wpr, g_wpr);
    round_kernel<<<(NM*NC/4 + 255)/256, 256>>>(x, d_xr, NM*NC/4);
    round_kernel<<<(N3C*NC/4 + 255)/256, 256>>>(w_att, d_war, N3C*NC/4);
    round_kernel<<<(NC*NC/4 + 255)/256, 256>>>(w_proj, d_wpr, NC*NC/4);

    // 1) QKV projection (tf32 mma, cp.async pipeline, 16 warps) -> q/k/v
    dim3 g1(N3C / 128, NM / 256);   // (48, 16)
    mgemm3_kernel<0><<<g1, 512, GEMM_SMEM>>>(b_att, nullptr);

    // 2) RoPE in-place on q, k
    rope_kernel<<<(2 * NB * NH * NT * (HD/2)) / 256, 256>>>();

    // 3) causal flash attention (tf32 mma) -> g_y [B,T,C]
    attn_kernel<<<dim3(NT / 128, NB * NH), 256, attn_smem>>>();

    // 4) output projection -> d_out
    dim3 g2(NC / 128, NM / 256);    // (16, 16)
    mgemm3_kernel<1><<<g2, 512, GEMM_SMEM>>>(b_proj, out);
}

// round 12
// speedup vs baseline: 1.0687x; 1.0687x over previous
#include <cuda_runtime.h>
#include <cstdint>
#include <math.h>

#define NB 2
#define NT 2048
#define NC 2048
#define NH 16
#define HD 128
#define NM (NB*NT)      /* 4096 rows */
#define N3C (3*NC)      /* 6144 */

// ---------------- scratch (device globals; no allocations allowed) ----------
__device__ float g_q[(size_t)NB*NH*NT*HD];
__device__ float g_k[(size_t)NB*NH*NT*HD];
__device__ float g_v[(size_t)NB*NH*NT*HD];
__device__ float g_y[(size_t)NM*NC];
__device__ float g_xr[(size_t)NM*NC];       // tf32-rounded x
__device__ float g_war[(size_t)N3C*NC];     // tf32-rounded w_att
__device__ float g_wpr[(size_t)NC*NC];      // tf32-rounded w_proj

// ---------------- helpers ----------------------------------------------------
__device__ __forceinline__ float to_tf32(float x) {
    float r;
    asm("cvt.rna.tf32.f32 %0, %1;" : "=f"(r) : "f"(x));
    return r;
}
__device__ __forceinline__ uint32_t smem_u32(const void* p) {
    uint32_t a;
    asm("{ .reg .u64 t; cvta.to.shared.u64 t, %1; cvt.u32.u64 %0, t; }"
        : "=r"(a) : "l"(p));
    return a;
}
__device__ __forceinline__ void cpasync16(uint32_t s, const void* g) {
    asm volatile("cp.async.cg.shared.global [%0], [%1], 16;" :: "r"(s), "l"(g));
}
#define CP_COMMIT()  asm volatile("cp.async.commit_group;" ::: "memory")
#define CP_WAIT1()   asm volatile("cp.async.wait_group 1;" ::: "memory")
#define CP_WAIT2()   asm volatile("cp.async.wait_group 2;" ::: "memory")

__device__ __forceinline__ void mma_tf32(float* c, const uint32_t* a, const uint32_t* b) {
    asm volatile(
        "mma.sync.aligned.m16n8k8.row.col.f32.tf32.tf32.f32 "
        "{%0,%1,%2,%3}, {%4,%5,%6,%7}, {%8,%9}, {%0,%1,%2,%3};"
        : "+f"(c[0]), "+f"(c[1]), "+f"(c[2]), "+f"(c[3])
        : "r"(a[0]), "r"(a[1]), "r"(a[2]), "r"(a[3]), "r"(b[0]), "r"(b[1]));
}

// fast exp for x <= 0: FMA/ALU pipes only.
__device__ __forceinline__ float fexp(float x) {
    float t = fmaxf(x * 1.442695041f, -126.0f);
    float r = t + 12582912.0f;
    float i = r - 12582912.0f;
    float f = t - i;
    float p =              1.3333558e-3f;
    p = fmaf(p, f, 9.6181291e-3f);
    p = fmaf(p, f, 5.5504109e-2f);
    p = fmaf(p, f, 2.4022651e-1f);
    p = fmaf(p, f, 6.9314718e-1f);
    p = fmaf(p, f, 1.0f);
    int sb = (__float_as_int(r) << 23) + 0x3F800000;
    return p * __int_as_float(sb);
}

// ---------------- pre-round inputs to tf32 (RNA) ------------------------------
__global__ void round_kernel(const float* __restrict__ in, float* __restrict__ out, int n4)
{
    int i = blockIdx.x * blockDim.x + threadIdx.x;
    if (i < n4) {
        float4 v = ((const float4*)in)[i];
        v.x = to_tf32(v.x); v.y = to_tf32(v.y);
        v.z = to_tf32(v.z); v.w = to_tf32(v.w);
        ((float4*)out)[i] = v;
    }
}

// ---------------- tf32 tensor-core GEMM v4: out = A @ W^T + bias --------------
// CTA 128(M) x 128(N), 8 warps as 2m x 4n of 64x32 warp tiles (acc=64 regs).
// 4-stage cp.async pipeline, K-chunk 16, smem row stride 20, 2 CTAs/SM.
// MODE 0: A=g_xr, W=g_war -> scatter to g_q/g_k/g_v. MODE 1: A=g_y, W=g_wpr -> out.
#define ASTRIDE 20
#define A_ST_FL (128*ASTRIDE)                 /* 2560 */
#define B_ST_FL (128*ASTRIDE)                 /* 2560 */
#define ST_FL   (A_ST_FL + B_ST_FL)           /* 5120 floats = 20480 B */
#define NSTAGE  4
#define GEMM_SMEM (NSTAGE*ST_FL*4)            /* 81920 B -> 2 CTAs/SM */

template<int MODE>
__global__ __launch_bounds__(256, 2)
void mgemm4_kernel(const float* __restrict__ bias, float* __restrict__ out)
{
    extern __shared__ float sm2[];
    const float* A = (MODE == 1) ? (const float*)g_y : (const float*)g_xr;
    const float* W = (MODE == 1) ? (const float*)g_wpr : (const float*)g_war;
    const int K = NC;

    const int tid = threadIdx.x;
    const int lane = tid & 31, wid = tid >> 5;       // wid 0..7
    const int qr = lane >> 2, qc = lane & 3;
    const int wm = (wid >> 2) * 64;                  // 2 m-warps
    const int wn = (wid & 3) * 32;                   // 4 n-warps
    const int m0 = blockIdx.y * 128;
    const int n0 = blockIdx.x * 128;

    // staging: thread -> rows (tid>>2) and (tid>>2)+64, 16B chunk (tid&3)
    const int srow = tid >> 2;                       // 0..63
    const int sch  = (tid & 3) * 4;
    const float* Ag = A + (size_t)(m0 + srow) * K + sch;
    const float* Wg = W + (size_t)(n0 + srow) * K + sch;
    const uint32_t sm_base = smem_u32(sm2);
    const uint32_t a_sm = sm_base + (uint32_t)(srow * ASTRIDE + sch) * 4;
    const uint32_t b_sm = a_sm + A_ST_FL * 4;
    const uint32_t rofs = (uint32_t)(64 * ASTRIDE) * 4;

    float acc[4][4][4];
#pragma unroll
    for (int i = 0; i < 4; i++)
#pragma unroll
        for (int j = 0; j < 4; j++)
#pragma unroll
            for (int v = 0; v < 4; v++) acc[i][j][v] = 0.f;

    const int NCHU = K / 16;   // 128

    // prologue: stages 0..2
#pragma unroll
    for (int s = 0; s < 3; s++) {
        const int k0 = s * 16;
        const uint32_t so = (uint32_t)(s * ST_FL) * 4;
        cpasync16(a_sm + so, Ag + k0);
        cpasync16(a_sm + so + rofs, Ag + (size_t)64 * K + k0);
        cpasync16(b_sm + so, Wg + k0);
        cpasync16(b_sm + so + rofs, Wg + (size_t)64 * K + k0);
        CP_COMMIT();
    }

    int stage = 0;        // stage of chunk c
    int nstage = 3;       // stage of chunk c+3
#pragma unroll 1
    for (int c = 0; c < NCHU; ++c) {
        CP_WAIT2();                 // chunk c resident (c+1, c+2 may fly)
        __syncthreads();

        // issue chunk c+3 into nstage (stage of c-1, fully consumed last iter)
        if (c + 3 < NCHU) {
            const int k0 = (c + 3) * 16;
            const uint32_t so = (uint32_t)(nstage * ST_FL) * 4;
            cpasync16(a_sm + so, Ag + k0);
            cpasync16(a_sm + so + rofs, Ag + (size_t)64 * K + k0);
            cpasync16(b_sm + so, Wg + k0);
            cpasync16(b_sm + so + rofs, Wg + (size_t)64 * K + k0);
        }
        CP_COMMIT();

        const float* as = sm2 + stage * ST_FL;
        const float* bs = as + A_ST_FL;
#pragma unroll
        for (int kk = 0; kk < 16; kk += 8) {
            uint32_t af[4][4];
#pragma unroll
            for (int i = 0; i < 4; i++) {
                const float* ap = as + (wm + i * 16 + qr) * ASTRIDE + kk + qc;
                af[i][0] = __float_as_uint(ap[0]);
                af[i][1] = __float_as_uint(ap[8 * ASTRIDE]);
                af[i][2] = __float_as_uint(ap[4]);
                af[i][3] = __float_as_uint(ap[8 * ASTRIDE + 4]);
            }
#pragma unroll
            for (int j = 0; j < 4; j++) {
                uint32_t bf[2];
                const float* bp = bs + (wn + j * 8 + qr) * ASTRIDE + kk + qc;
                bf[0] = __float_as_uint(bp[0]);
                bf[1] = __float_as_uint(bp[4]);
#pragma unroll
                for (int i = 0; i < 4; i++)
                    mma_tf32(acc[i][j], af[i], bf);
            }
        }

        stage = (stage == NSTAGE - 1) ? 0 : stage + 1;
        nstage = (nstage == NSTAGE - 1) ? 0 : nstage + 1;
    }

    // ---- epilogue: add bias, store ----
#pragma unroll
    for (int i = 0; i < 4; i++) {
#pragma unroll
        for (int j = 0; j < 4; j++) {
            const int ncol = n0 + wn + j * 8 + (qc << 1);
            const float b0 = bias[ncol], b1 = bias[ncol + 1];
            const int r0 = m0 + wm + i * 16 + qr;
            float2 lo = make_float2(acc[i][j][0] + b0, acc[i][j][1] + b1);
            float2 hi = make_float2(acc[i][j][2] + b0, acc[i][j][3] + b1);
            if (MODE == 0) {
                const int which = ncol >> 11;
                const int h = (ncol >> 7) & 15;
                const int d = ncol & 127;
                float* dst = (which == 0) ? g_q : ((which == 1) ? g_k : g_v);
                if (which == 2) {   // v feeds tf32 MMA directly: pre-round
                    lo.x = to_tf32(lo.x); lo.y = to_tf32(lo.y);
                    hi.x = to_tf32(hi.x); hi.y = to_tf32(hi.y);
                }
                int bb = r0 >> 11, t0 = r0 & 2047;
                *(float2*)&dst[(((size_t)bb * NH + h) * NT + t0) * HD + d] = lo;
                const int r1 = r0 + 8;
                bb = r1 >> 11; t0 = r1 & 2047;
                *(float2*)&dst[(((size_t)bb * NH + h) * NT + t0) * HD + d] = hi;
            } else {
                *(float2*)&out[(size_t)r0 * NC + ncol] = lo;
                *(float2*)&out[(size_t)(r0 + 8) * NC + ncol] = hi;
            }
        }
    }
}

// ---------------- RoPE (in-place; q pre-scaled by 1/sqrt(D); tf32-rounded) ---
__global__ void rope_kernel()
{
    int idx = blockIdx.x * blockDim.x + threadIdx.x;
    int pair  = idx & 63;
    int row   = (idx >> 6) & (NB*NH*NT - 1);
    int which = idx >> 22;
    float* buf = which ? g_k : g_q;
    int t = row & (NT - 1);
    float theta = powf(10000.0f, -(float)(2 * pair) * (1.0f / 128.0f));
    float fr = (float)t * theta;
    float s, c;
    sincosf(fr, &s, &c);
    size_t off = (size_t)row * 64 + pair;
    float2 v = ((float2*)buf)[off];
    float ox = v.x * c - v.y * s;
    float oy = v.x * s + v.y * c;
    if (which == 0) {
        const float scale = 0.08838834764831845f;
        ox *= scale; oy *= scale;
    }
    float2 o;
    o.x = to_tf32(ox);
    o.y = to_tf32(oy);
    ((float2*)buf)[off] = o;
}

// ---------------- Flash attention (tf32 mma, causal) -------------------------
#define AQS 132
#define AKS 132
#define AVS 136
#define APS 76
#define OFF_Q 0
#define OFF_K (128*AQS)
#define OFF_V (OFF_K + 2*64*AKS)
#define OFF_P (OFF_V + 64*AVS)
#define ATTN_FLOATS (OFF_P + 128*APS)

__global__ __launch_bounds__(256)
void attn_kernel()
{
    extern __shared__ float sm[];
    const uint32_t sb = smem_u32(sm);
    const int tid = threadIdx.x;
    const int lane = tid & 31, w = tid >> 5;
    const int qrow = lane >> 2, qcol = lane & 3;
    const int bh = blockIdx.y;
    const int qt = (gridDim.x - 1) - blockIdx.x;
    const int q0 = qt * 128;
    const float* Qg = g_q + (size_t)bh * NT * HD + (size_t)q0 * HD;
    const float* Kg = g_k + (size_t)bh * NT * HD;
    const float* Vg = g_v + (size_t)bh * NT * HD;

    for (int c = tid; c < 128 * 32; c += 256) {
        int row = c >> 5, ch = (c & 31) * 4;
        asm volatile("cp.async.ca.shared.global [%0], [%1], 16;"
            :: "r"(sb + (uint32_t)(OFF_Q + row * AQS + ch) * 4),
               "l"(Qg + (size_t)row * HD + ch));
    }
    for (int c = tid; c < 64 * 32; c += 256) {
        int row = c >> 5, ch = (c & 31) * 4;
        asm volatile("cp.async.ca.shared.global [%0], [%1], 16;"
            :: "r"(sb + (uint32_t)(OFF_K + row * AKS + ch) * 4),
               "l"(Kg + (size_t)row * HD + ch));
    }
    CP_COMMIT();
    for (int c = tid; c < 64 * 32; c += 256) {
        int row = c >> 5, ch = (c & 31) * 4;
        asm volatile("cp.async.ca.shared.global [%0], [%1], 16;"
            :: "r"(sb + (uint32_t)(OFF_V + row * AVS + ch) * 4),
               "l"(Vg + (size_t)row * HD + ch));
    }
    CP_COMMIT();

    float o[16][4];
#pragma unroll
    for (int jd = 0; jd < 16; jd++)
#pragma unroll
        for (int v = 0; v < 4; v++) o[jd][v] = 0.f;
    float m0 = -1e30f, m1 = -1e30f, l0 = 0.f, l1 = 0.f;
    const int r_lo = 16 * w + qrow;

    const float* qs = sm + OFF_Q + (16 * w) * AQS;
    float* psw = sm + OFF_P + (16 * w) * APS;

    const int nkt = (qt + 1) * 2;
    for (int kt = 0; kt < nkt; ++kt) {
        const int k0 = kt * 64;
        const int kb = kt & 1;

        CP_WAIT1();
        __syncthreads();

        if (kt + 1 < nkt) {
            const float* Kn = Kg + (size_t)(k0 + 64) * HD;
            uint32_t kdst = sb + (uint32_t)(OFF_K + (kb ^ 1) * 64 * AKS) * 4;
            for (int c = tid; c < 64 * 32; c += 256) {
                int row = c >> 5, ch = (c & 31) * 4;
                asm volatile("cp.async.ca.shared.global [%0], [%1], 16;"
                    :: "r"(kdst + (uint32_t)(row * AKS + ch) * 4),
                       "l"(Kn + (size_t)row * HD + ch));
            }
        }
        CP_COMMIT();

        float s[8][4];
#pragma unroll
        for (int j = 0; j < 8; j++)
#pragma unroll
            for (int v = 0; v < 4; v++) s[j][v] = 0.f;

        const float* ks = sm + OFF_K + kb * 64 * AKS;
#pragma unroll
        for (int kk = 0; kk < 16; ++kk) {
            const int kc = kk * 8;
            uint32_t a[4];
            a[0] = __float_as_uint(qs[qrow * AQS + kc + qcol]);
            a[1] = __float_as_uint(qs[(qrow + 8) * AQS + kc + qcol]);
            a[2] = __float_as_uint(qs[qrow * AQS + kc + qcol + 4]);
            a[3] = __float_as_uint(qs[(qrow + 8) * AQS + kc + qcol + 4]);
#pragma unroll
            for (int j = 0; j < 8; j++) {
                uint32_t b[2];
                b[0] = __float_as_uint(ks[(8 * j + qrow) * AKS + kc + qcol]);
                b[1] = __float_as_uint(ks[(8 * j + qrow) * AKS + kc + qcol + 4]);
                mma_tf32(s[j], a, b);
            }
        }

        if (k0 + 64 > q0) {
            const int row0 = q0 + r_lo;
#pragma unroll
            for (int j = 0; j < 8; j++) {
                const int key = k0 + 8 * j + 2 * qcol;
                if (key     > row0)     s[j][0] = -1e30f;
                if (key + 1 > row0)     s[j][1] = -1e30f;
                if (key     > row0 + 8) s[j][2] = -1e30f;
                if (key + 1 > row0 + 8) s[j][3] = -1e30f;
            }
        }

        float mx0 = -1e30f, mx1 = -1e30f;
#pragma unroll
        for (int j = 0; j < 8; j++) {
            mx0 = fmaxf(mx0, fmaxf(s[j][0], s[j][1]));
            mx1 = fmaxf(mx1, fmaxf(s[j][2], s[j][3]));
        }
        mx0 = fmaxf(mx0, __shfl_xor_sync(0xffffffffu, mx0, 1));
        mx0 = fmaxf(mx0, __shfl_xor_sync(0xffffffffu, mx0, 2));
        mx1 = fmaxf(mx1, __shfl_xor_sync(0xffffffffu, mx1, 1));
        mx1 = fmaxf(mx1, __shfl_xor_sync(0xffffffffu, mx1, 2));
        const float mn0 = fmaxf(m0, mx0), mn1 = fmaxf(m1, mx1);
        const float fac0 = fexp(m0 - mn0), fac1 = fexp(m1 - mn1);
        m0 = mn0; m1 = mn1;

        float sum0 = 0.f, sum1 = 0.f;
#pragma unroll
        for (int j = 0; j < 8; j++) {
            float p00 = fexp(s[j][0] - mn0);
            float p01 = fexp(s[j][1] - mn0);
            float p10 = fexp(s[j][2] - mn1);
            float p11 = fexp(s[j][3] - mn1);
            sum0 += p00 + p01;
            sum1 += p10 + p11;
            *(float2*)&psw[qrow * APS + 8 * j + 2 * qcol] =
                make_float2(to_tf32(p00), to_tf32(p01));
            *(float2*)&psw[(qrow + 8) * APS + 8 * j + 2 * qcol] =
                make_float2(to_tf32(p10), to_tf32(p11));
        }
        sum0 += __shfl_xor_sync(0xffffffffu, sum0, 1);
        sum0 += __shfl_xor_sync(0xffffffffu, sum0, 2);
        sum1 += __shfl_xor_sync(0xffffffffu, sum1, 1);
        sum1 += __shfl_xor_sync(0xffffffffu, sum1, 2);
        l0 = l0 * fac0 + sum0;
        l1 = l1 * fac1 + sum1;

#pragma unroll
        for (int jd = 0; jd < 16; jd++) {
            o[jd][0] *= fac0; o[jd][1] *= fac0;
            o[jd][2] *= fac1; o[jd][3] *= fac1;
        }
        __syncwarp();

        CP_WAIT1();
        __syncthreads();

        const float* vs = sm + OFF_V;
#pragma unroll
        for (int kk = 0; kk < 8; ++kk) {
            const int kc = kk * 8;
            uint32_t a[4];
            a[0] = __float_as_uint(psw[qrow * APS + kc + qcol]);
            a[1] = __float_as_uint(psw[(qrow + 8) * APS + kc + qcol]);
            a[2] = __float_as_uint(psw[qrow * APS + kc + qcol + 4]);
            a[3] = __float_as_uint(psw[(qrow + 8) * APS + kc + qcol + 4]);
#pragma unroll
            for (int jd = 0; jd < 16; jd++) {
                uint32_t b[2];
                b[0] = __float_as_uint(vs[(kc + qcol) * AVS + 8 * jd + qrow]);
                b[1] = __float_as_uint(vs[(kc + qcol + 4) * AVS + 8 * jd + qrow]);
                mma_tf32(o[jd], a, b);
            }
        }

        __syncthreads();

        if (kt + 1 < nkt) {
            const float* Vn = Vg + (size_t)(k0 + 64) * HD;
            for (int c = tid; c < 64 * 32; c += 256) {
                int row = c >> 5, ch = (c & 31) * 4;
                asm volatile("cp.async.ca.shared.global [%0], [%1], 16;"
                    :: "r"(sb + (uint32_t)(OFF_V + row * AVS + ch) * 4),
                       "l"(Vn + (size_t)row * HD + ch));
            }
            CP_COMMIT();
        }
    }

    // epilogue: O / l -> g_y [B,T,C], pre-rounded to tf32 for the proj GEMM
    const float il0 = 1.0f / l0, il1 = 1.0f / l1;
    const int bb = bh >> 4, h = bh & 15;
    const int t0g = q0 + r_lo;
    float* y0 = g_y + ((size_t)bb * NT + t0g) * NC + h * HD;
    float* y1 = g_y + ((size_t)bb * NT + t0g + 8) * NC + h * HD;
#pragma unroll
    for (int jd = 0; jd < 16; jd++) {
        const int d = 8 * jd + 2 * qcol;
        *(float2*)&y0[d] = make_float2(to_tf32(o[jd][0] * il0), to_tf32(o[jd][1] * il0));
        *(float2*)&y1[d] = make_float2(to_tf32(o[jd][2] * il1), to_tf32(o[jd][3] * il1));
    }
}

// ---------------- launch ------------------------------------------------------
extern "C" void kernel_launch(void* const* d_in, const int* in_sizes, int n_in,
                              void* d_out, int out_size)
{
    const float* x      = (const float*)d_in[0];
    const float* w_att  = (const float*)d_in[1];
    const float* b_att  = (const float*)d_in[2];
    const float* w_proj = (const float*)d_in[3];
    const float* b_proj = (const float*)d_in[4];
    float* out = (float*)d_out;

    cudaFuncSetAttribute(mgemm4_kernel<0>,
                         cudaFuncAttributeMaxDynamicSharedMemorySize, GEMM_SMEM);
    cudaFuncSetAttribute(mgemm4_kernel<1>,
                         cudaFuncAttributeMaxDynamicSharedMemorySize, GEMM_SMEM);
    const int attn_smem = ATTN_FLOATS * (int)sizeof(float);
    cudaFuncSetAttribute(attn_kernel,
                         cudaFuncAttributeMaxDynamicSharedMemorySize, attn_smem);

    // 0) pre-round inputs to tf32 (RNA) scratch copies
    float* d_xr;  cudaGetSymbolAddress((void**)&d_xr,  g_xr);
    float* d_war; cudaGetSymbolAddress((void**)&d_war, g_war);
    float* d_wpr; cudaGetSymbolAddress((void**)&d_wpr, g_wpr);
    round_kernel<<<(NM*NC/4 + 255)/256, 256>>>(x, d_xr, NM*NC/4);
    round_kernel<<<(N3C*NC/4 + 255)/256, 256>>>(w_att, d_war, N3C*NC/4);
    round_kernel<<<(NC*NC/4 + 255)/256, 256>>>(w_proj, d_wpr, NC*NC/4);

    // 1) QKV projection (tf32 mma, 2 CTAs/SM) -> q/k/v
    dim3 g1(N3C / 128, NM / 128);   // (48, 32)
    mgemm4_kernel<0><<<g1, 256, GEMM_SMEM>>>(b_att, nullptr);

    // 2) RoPE in-place on q, k
    rope_kernel<<<(2 * NB * NH * NT * (HD/2)) / 256, 256>>>();

    // 3) causal flash attention (tf32 mma) -> g_y [B,T,C]
    attn_kernel<<<dim3(NT / 128, NB * NH), 256, attn_smem>>>();

    // 4) output projection -> d_out
    dim3 g2(NC / 128, NM / 128);    // (16, 32)
    mgemm4_kernel<1><<<g2, 256, GEMM_SMEM>>>(b_proj, out);
}

// round 13
// speedup vs baseline: 1.6271x; 1.5225x over previous
#include <cuda_runtime.h>
#include <cuda_fp16.h>
#include <cstdint>
#include <math.h>

#define NB 2
#define NT 2048
#define NC 2048
#define NH 16
#define HD 128
#define NM (NB*NT)      /* 4096 rows */
#define N3C (3*NC)      /* 6144 */

// ---------------- scratch (device globals; no allocations allowed) ----------
__device__ float  g_q[(size_t)NB*NH*NT*HD];
__device__ float  g_k[(size_t)NB*NH*NT*HD];
__device__ float  g_v[(size_t)NB*NH*NT*HD];
__device__ __half g_yh[(size_t)NM*NC];      // fp16 attention output
__device__ __half g_xh[(size_t)NM*NC];      // fp16 x
__device__ __half g_wah[(size_t)N3C*NC];    // fp16 w_att
__device__ __half g_wph[(size_t)NC*NC];     // fp16 w_proj

// ---------------- helpers ----------------------------------------------------
__device__ __forceinline__ float to_tf32(float x) {
    float r;
    asm("cvt.rna.tf32.f32 %0, %1;" : "=f"(r) : "f"(x));
    return r;
}
__device__ __forceinline__ uint32_t smem_u32(const void* p) {
    uint32_t a;
    asm("{ .reg .u64 t; cvta.to.shared.u64 t, %1; cvt.u32.u64 %0, t; }"
        : "=r"(a) : "l"(p));
    return a;
}
__device__ __forceinline__ void cpasync16(uint32_t s, const void* g) {
    asm volatile("cp.async.cg.shared.global [%0], [%1], 16;" :: "r"(s), "l"(g));
}
#define CP_COMMIT()  asm volatile("cp.async.commit_group;" ::: "memory")
#define CP_WAIT1()   asm volatile("cp.async.wait_group 1;" ::: "memory")
#define CP_WAIT2()   asm volatile("cp.async.wait_group 2;" ::: "memory")

__device__ __forceinline__ void mma_tf32(float* c, const uint32_t* a, const uint32_t* b) {
    asm volatile(
        "mma.sync.aligned.m16n8k8.row.col.f32.tf32.tf32.f32 "
        "{%0,%1,%2,%3}, {%4,%5,%6,%7}, {%8,%9}, {%0,%1,%2,%3};"
        : "+f"(c[0]), "+f"(c[1]), "+f"(c[2]), "+f"(c[3])
        : "r"(a[0]), "r"(a[1]), "r"(a[2]), "r"(a[3]), "r"(b[0]), "r"(b[1]));
}
__device__ __forceinline__ void mma_f16(float* c, const uint32_t* a, const uint32_t* b) {
    asm volatile(
        "mma.sync.aligned.m16n8k16.row.col.f32.f16.f16.f32 "
        "{%0,%1,%2,%3}, {%4,%5,%6,%7}, {%8,%9}, {%0,%1,%2,%3};"
        : "+f"(c[0]), "+f"(c[1]), "+f"(c[2]), "+f"(c[3])
        : "r"(a[0]), "r"(a[1]), "r"(a[2]), "r"(a[3]), "r"(b[0]), "r"(b[1]));
}

// fast exp for x <= 0: FMA/ALU pipes only.
__device__ __forceinline__ float fexp(float x) {
    float t = fmaxf(x * 1.442695041f, -126.0f);
    float r = t + 12582912.0f;
    float i = r - 12582912.0f;
    float f = t - i;
    float p =              1.3333558e-3f;
    p = fmaf(p, f, 9.6181291e-3f);
    p = fmaf(p, f, 5.5504109e-2f);
    p = fmaf(p, f, 2.4022651e-1f);
    p = fmaf(p, f, 6.9314718e-1f);
    p = fmaf(p, f, 1.0f);
    int sb = (__float_as_int(r) << 23) + 0x3F800000;
    return p * __int_as_float(sb);
}

// ---------------- convert inputs to fp16 (RNE) --------------------------------
__global__ void round_h_kernel(const float* __restrict__ in, __half* __restrict__ out, int n4)
{
    int i = blockIdx.x * blockDim.x + threadIdx.x;
    if (i < n4) {
        float4 v = ((const float4*)in)[i];
        __half2 h0 = __floats2half2_rn(v.x, v.y);
        __half2 h1 = __floats2half2_rn(v.z, v.w);
        uint2 u;
        u.x = *(uint32_t*)&h0;
        u.y = *(uint32_t*)&h1;
        ((uint2*)out)[i] = u;
    }
}

// ---------------- fp16 tensor-core GEMM v5: out = A @ W^T + bias --------------
// CTA 128(M) x 128(N), 8 warps as 2m x 4n of 64x32 warp tiles (acc=64 regs).
// K-chunk 32 halves (64B/row), 4-stage cp.async, row stride 40 halves (80B),
// 2 CTAs/SM. MODE 0: A=g_xh, W=g_wah -> scatter q/k/v. MODE 1: A=g_yh, W=g_wph.
#define HSTRIDE 40
#define A_ST_H (128*HSTRIDE)                  /* 5120 halves = 10240 B */
#define ST_H   (2*A_ST_H)                     /* per stage: 20480 B */
#define NSTAGE 4
#define GEMM_SMEM (NSTAGE*ST_H*2)             /* 81920 B -> 2 CTAs/SM */

template<int MODE>
__global__ __launch_bounds__(256, 2)
void mgemm5_kernel(const float* __restrict__ bias, float* __restrict__ out)
{
    extern __shared__ __half smh[];
    const __half* A = (MODE == 1) ? (const __half*)g_yh : (const __half*)g_xh;
    const __half* W = (MODE == 1) ? (const __half*)g_wph : (const __half*)g_wah;
    const int K = NC;

    const int tid = threadIdx.x;
    const int lane = tid & 31, wid = tid >> 5;       // wid 0..7
    const int qr = lane >> 2, qc = lane & 3;
    const int wm = (wid >> 2) * 64;                  // 2 m-warps
    const int wn = (wid & 3) * 32;                   // 4 n-warps
    const int m0 = blockIdx.y * 128;
    const int n0 = blockIdx.x * 128;

    // staging: rows (tid>>2) and +64; 16B chunk (tid&3) of the 64B row
    const int srow = tid >> 2;                       // 0..63
    const int sch  = (tid & 3) * 8;                  // halves
    const __half* Ag = A + (size_t)(m0 + srow) * K + sch;
    const __half* Wg = W + (size_t)(n0 + srow) * K + sch;
    const uint32_t sm_base = smem_u32(smh);
    const uint32_t a_sm = sm_base + (uint32_t)(srow * HSTRIDE + sch) * 2;
    const uint32_t b_sm = a_sm + A_ST_H * 2;
    const uint32_t rofs = (uint32_t)(64 * HSTRIDE) * 2;

    float acc[4][4][4];
#pragma unroll
    for (int i = 0; i < 4; i++)
#pragma unroll
        for (int j = 0; j < 4; j++)
#pragma unroll
            for (int v = 0; v < 4; v++) acc[i][j][v] = 0.f;

    const int NCHU = K / 32;   // 64 chunks of 32 halves

    // prologue: stages 0..2
#pragma unroll
    for (int s = 0; s < 3; s++) {
        const int k0 = s * 32;
        const uint32_t so = (uint32_t)(s * ST_H) * 2;
        cpasync16(a_sm + so, Ag + k0);
        cpasync16(a_sm + so + rofs, Ag + (size_t)64 * K + k0);
        cpasync16(b_sm + so, Wg + k0);
        cpasync16(b_sm + so + rofs, Wg + (size_t)64 * K + k0);
        CP_COMMIT();
    }

    int stage = 0;        // stage of chunk c
    int nstage = 3;       // stage of chunk c+3
#pragma unroll 1
    for (int c = 0; c < NCHU; ++c) {
        CP_WAIT2();
        __syncthreads();

        if (c + 3 < NCHU) {
            const int k0 = (c + 3) * 32;
            const uint32_t so = (uint32_t)(nstage * ST_H) * 2;
            cpasync16(a_sm + so, Ag + k0);
            cpasync16(a_sm + so + rofs, Ag + (size_t)64 * K + k0);
            cpasync16(b_sm + so, Wg + k0);
            cpasync16(b_sm + so + rofs, Wg + (size_t)64 * K + k0);
        }
        CP_COMMIT();

        const __half* as = smh + stage * ST_H;
        const __half* bs = as + A_ST_H;
#pragma unroll
        for (int kb = 0; kb < 32; kb += 16) {
            uint32_t af[4][4];
#pragma unroll
            for (int i = 0; i < 4; i++) {
                const __half* ap = as + (wm + i * 16 + qr) * HSTRIDE + kb + 2 * qc;
                af[i][0] = *(const uint32_t*)(ap);
                af[i][1] = *(const uint32_t*)(ap + 8 * HSTRIDE);
                af[i][2] = *(const uint32_t*)(ap + 8);
                af[i][3] = *(const uint32_t*)(ap + 8 * HSTRIDE + 8);
            }
#pragma unroll
            for (int j = 0; j < 4; j++) {
                uint32_t bf[2];
                const __half* bp = bs + (wn + j * 8 + qr) * HSTRIDE + kb + 2 * qc;
                bf[0] = *(const uint32_t*)(bp);
                bf[1] = *(const uint32_t*)(bp + 8);
#pragma unroll
                for (int i = 0; i < 4; i++)
                    mma_f16(acc[i][j], af[i], bf);
            }
        }

        stage = (stage == NSTAGE - 1) ? 0 : stage + 1;
        nstage = (nstage == NSTAGE - 1) ? 0 : nstage + 1;
    }

    // ---- epilogue: add bias, store ----
#pragma unroll
    for (int i = 0; i < 4; i++) {
#pragma unroll
        for (int j = 0; j < 4; j++) {
            const int ncol = n0 + wn + j * 8 + (qc << 1);
            const float b0 = bias[ncol], b1 = bias[ncol + 1];
            const int r0 = m0 + wm + i * 16 + qr;
            float2 lo = make_float2(acc[i][j][0] + b0, acc[i][j][1] + b1);
            float2 hi = make_float2(acc[i][j][2] + b0, acc[i][j][3] + b1);
            if (MODE == 0) {
                const int which = ncol >> 11;
                const int h = (ncol >> 7) & 15;
                const int d = ncol & 127;
                float* dst = (which == 0) ? g_q : ((which == 1) ? g_k : g_v);
                if (which == 2) {   // v feeds tf32 MMA directly: pre-round
                    lo.x = to_tf32(lo.x); lo.y = to_tf32(lo.y);
                    hi.x = to_tf32(hi.x); hi.y = to_tf32(hi.y);
                }
                int bb = r0 >> 11, t0 = r0 & 2047;
                *(float2*)&dst[(((size_t)bb * NH + h) * NT + t0) * HD + d] = lo;
                const int r1 = r0 + 8;
                bb = r1 >> 11; t0 = r1 & 2047;
                *(float2*)&dst[(((size_t)bb * NH + h) * NT + t0) * HD + d] = hi;
            } else {
                *(float2*)&out[(size_t)r0 * NC + ncol] = lo;
                *(float2*)&out[(size_t)(r0 + 8) * NC + ncol] = hi;
            }
        }
    }
}

// ---------------- RoPE (in-place; q pre-scaled by 1/sqrt(D); tf32-rounded) ---
__global__ void rope_kernel()
{
    int idx = blockIdx.x * blockDim.x + threadIdx.x;
    int pair  = idx & 63;
    int row   = (idx >> 6) & (NB*NH*NT - 1);
    int which = idx >> 22;
    float* buf = which ? g_k : g_q;
    int t = row & (NT - 1);
    float theta = powf(10000.0f, -(float)(2 * pair) * (1.0f / 128.0f));
    float fr = (float)t * theta;
    float s, c;
    sincosf(fr, &s, &c);
    size_t off = (size_t)row * 64 + pair;
    float2 v = ((float2*)buf)[off];
    float ox = v.x * c - v.y * s;
    float oy = v.x * s + v.y * c;
    if (which == 0) {
        const float scale = 0.08838834764831845f;
        ox *= scale; oy *= scale;
    }
    float2 o;
    o.x = to_tf32(ox);
    o.y = to_tf32(oy);
    ((float2*)buf)[off] = o;
}

// ---------------- Flash attention (tf32 mma, causal) -------------------------
#define AQS 132
#define AKS 132
#define AVS 136
#define APS 76
#define OFF_Q 0
#define OFF_K (128*AQS)
#define OFF_V (OFF_K + 2*64*AKS)
#define OFF_P (OFF_V + 64*AVS)
#define ATTN_FLOATS (OFF_P + 128*APS)

__global__ __launch_bounds__(256)
void attn_kernel()
{
    extern __shared__ float sm[];
    const uint32_t sb = smem_u32(sm);
    const int tid = threadIdx.x;
    const int lane = tid & 31, w = tid >> 5;
    const int qrow = lane >> 2, qcol = lane & 3;
    const int bh = blockIdx.y;
    const int qt = (gridDim.x - 1) - blockIdx.x;
    const int q0 = qt * 128;
    const float* Qg = g_q + (size_t)bh * NT * HD + (size_t)q0 * HD;
    const float* Kg = g_k + (size_t)bh * NT * HD;
    const float* Vg = g_v + (size_t)bh * NT * HD;

    for (int c = tid; c < 128 * 32; c += 256) {
        int row = c >> 5, ch = (c & 31) * 4;
        asm volatile("cp.async.ca.shared.global [%0], [%1], 16;"
            :: "r"(sb + (uint32_t)(OFF_Q + row * AQS + ch) * 4),
               "l"(Qg + (size_t)row * HD + ch));
    }
    for (int c = tid; c < 64 * 32; c += 256) {
        int row = c >> 5, ch = (c & 31) * 4;
        asm volatile("cp.async.ca.shared.global [%0], [%1], 16;"
            :: "r"(sb + (uint32_t)(OFF_K + row * AKS + ch) * 4),
               "l"(Kg + (size_t)row * HD + ch));
    }
    CP_COMMIT();
    for (int c = tid; c < 64 * 32; c += 256) {
        int row = c >> 5, ch = (c & 31) * 4;
        asm volatile("cp.async.ca.shared.global [%0], [%1], 16;"
            :: "r"(sb + (uint32_t)(OFF_V + row * AVS + ch) * 4),
               "l"(Vg + (size_t)row * HD + ch));
    }
    CP_COMMIT();

    float o[16][4];
#pragma unroll
    for (int jd = 0; jd < 16; jd++)
#pragma unroll
        for (int v = 0; v < 4; v++) o[jd][v] = 0.f;
    float m0 = -1e30f, m1 = -1e30f, l0 = 0.f, l1 = 0.f;
    const int r_lo = 16 * w + qrow;

    const float* qs = sm + OFF_Q + (16 * w) * AQS;
    float* psw = sm + OFF_P + (16 * w) * APS;

    const int nkt = (qt + 1) * 2;
    for (int kt = 0; kt < nkt; ++kt) {
        const int k0 = kt * 64;
        const int kb = kt & 1;

        CP_WAIT1();
        __syncthreads();

        if (kt + 1 < nkt) {
            const float* Kn = Kg + (size_t)(k0 + 64) * HD;
            uint32_t kdst = sb + (uint32_t)(OFF_K + (kb ^ 1) * 64 * AKS) * 4;
            for (int c = tid; c < 64 * 32; c += 256) {
                int row = c >> 5, ch = (c & 31) * 4;
                asm volatile("cp.async.ca.shared.global [%0], [%1], 16;"
                    :: "r"(kdst + (uint32_t)(row * AKS + ch) * 4),
                       "l"(Kn + (size_t)row * HD + ch));
            }
        }
        CP_COMMIT();

        float s[8][4];
#pragma unroll
        for (int j = 0; j < 8; j++)
#pragma unroll
            for (int v = 0; v < 4; v++) s[j][v] = 0.f;

        const float* ks = sm + OFF_K + kb * 64 * AKS;
#pragma unroll
        for (int kk = 0; kk < 16; ++kk) {
            const int kc = kk * 8;
            uint32_t a[4];
            a[0] = __float_as_uint(qs[qrow * AQS + kc + qcol]);
            a[1] = __float_as_uint(qs[(qrow + 8) * AQS + kc + qcol]);
            a[2] = __float_as_uint(qs[qrow * AQS + kc + qcol + 4]);
            a[3] = __float_as_uint(qs[(qrow + 8) * AQS + kc + qcol + 4]);
#pragma unroll
            for (int j = 0; j < 8; j++) {
                uint32_t b[2];
                b[0] = __float_as_uint(ks[(8 * j + qrow) * AKS + kc + qcol]);
                b[1] = __float_as_uint(ks[(8 * j + qrow) * AKS + kc + qcol + 4]);
                mma_tf32(s[j], a, b);
            }
        }

        if (k0 + 64 > q0) {
            const int row0 = q0 + r_lo;
#pragma unroll
            for (int j = 0; j < 8; j++) {
                const int key = k0 + 8 * j + 2 * qcol;
                if (key     > row0)     s[j][0] = -1e30f;
                if (key + 1 > row0)     s[j][1] = -1e30f;
                if (key     > row0 + 8) s[j][2] = -1e30f;
                if (key + 1 > row0 + 8) s[j][3] = -1e30f;
            }
        }

        float mx0 = -1e30f, mx1 = -1e30f;
#pragma unroll
        for (int j = 0; j < 8; j++) {
            mx0 = fmaxf(mx0, fmaxf(s[j][0], s[j][1]));
            mx1 = fmaxf(mx1, fmaxf(s[j][2], s[j][3]));
        }
        mx0 = fmaxf(mx0, __shfl_xor_sync(0xffffffffu, mx0, 1));
        mx0 = fmaxf(mx0, __shfl_xor_sync(0xffffffffu, mx0, 2));
        mx1 = fmaxf(mx1, __shfl_xor_sync(0xffffffffu, mx1, 1));
        mx1 = fmaxf(mx1, __shfl_xor_sync(0xffffffffu, mx1, 2));
        const float mn0 = fmaxf(m0, mx0), mn1 = fmaxf(m1, mx1);
        const float fac0 = fexp(m0 - mn0), fac1 = fexp(m1 - mn1);
        m0 = mn0; m1 = mn1;

        float sum0 = 0.f, sum1 = 0.f;
#pragma unroll
        for (int j = 0; j < 8; j++) {
            float p00 = fexp(s[j][0] - mn0);
            float p01 = fexp(s[j][1] - mn0);
            float p10 = fexp(s[j][2] - mn1);
            float p11 = fexp(s[j][3] - mn1);
            sum0 += p00 + p01;
            sum1 += p10 + p11;
            *(float2*)&psw[qrow * APS + 8 * j + 2 * qcol] =
                make_float2(to_tf32(p00), to_tf32(p01));
            *(float2*)&psw[(qrow + 8) * APS + 8 * j + 2 * qcol] =
                make_float2(to_tf32(p10), to_tf32(p11));
        }
        sum0 += __shfl_xor_sync(0xffffffffu, sum0, 1);
        sum0 += __shfl_xor_sync(0xffffffffu, sum0, 2);
        sum1 += __shfl_xor_sync(0xffffffffu, sum1, 1);
        sum1 += __shfl_xor_sync(0xffffffffu, sum1, 2);
        l0 = l0 * fac0 + sum0;
        l1 = l1 * fac1 + sum1;

#pragma unroll
        for (int jd = 0; jd < 16; jd++) {
            o[jd][0] *= fac0; o[jd][1] *= fac0;
            o[jd][2] *= fac1; o[jd][3] *= fac1;
        }
        __syncwarp();

        CP_WAIT1();
        __syncthreads();

        const float* vs = sm + OFF_V;
#pragma unroll
        for (int kk = 0; kk < 8; ++kk) {
            const int kc = kk * 8;
            uint32_t a[4];
            a[0] = __float_as_uint(psw[qrow * APS + kc + qcol]);
            a[1] = __float_as_uint(psw[(qrow + 8) * APS + kc + qcol]);
            a[2] = __float_as_uint(psw[qrow * APS + kc + qcol + 4]);
            a[3] = __float_as_uint(psw[(qrow + 8) * APS + kc + qcol + 4]);
#pragma unroll
            for (int jd = 0; jd < 16; jd++) {
                uint32_t b[2];
                b[0] = __float_as_uint(vs[(kc + qcol) * AVS + 8 * jd + qrow]);
                b[1] = __float_as_uint(vs[(kc + qcol + 4) * AVS + 8 * jd + qrow]);
                mma_tf32(o[jd], a, b);
            }
        }

        __syncthreads();

        if (kt + 1 < nkt) {
            const float* Vn = Vg + (size_t)(k0 + 64) * HD;
            for (int c = tid; c < 64 * 32; c += 256) {
                int row = c >> 5, ch = (c & 31) * 4;
                asm volatile("cp.async.ca.shared.global [%0], [%1], 16;"
                    :: "r"(sb + (uint32_t)(OFF_V + row * AVS + ch) * 4),
                       "l"(Vn + (size_t)row * HD + ch));
            }
            CP_COMMIT();
        }
    }

    // epilogue: O / l -> g_yh [B,T,C] (fp16 for the proj GEMM)
    const float il0 = 1.0f / l0, il1 = 1.0f / l1;
    const int bb = bh >> 4, h = bh & 15;
    const int t0g = q0 + r_lo;
    __half* y0 = g_yh + ((size_t)bb * NT + t0g) * NC + h * HD;
    __half* y1 = g_yh + ((size_t)bb * NT + t0g + 8) * NC + h * HD;
#pragma unroll
    for (int jd = 0; jd < 16; jd++) {
        const int d = 8 * jd + 2 * qcol;
        __half2 h0 = __floats2half2_rn(o[jd][0] * il0, o[jd][1] * il0);
        __half2 h1 = __floats2half2_rn(o[jd][2] * il1, o[jd][3] * il1);
        *(__half2*)&y0[d] = h0;
        *(__half2*)&y1[d] = h1;
    }
}

// ---------------- launch ------------------------------------------------------
extern "C" void kernel_launch(void* const* d_in, const int* in_sizes, int n_in,
                              void* d_out, int out_size)
{
    const float* x      = (const float*)d_in[0];
    const float* w_att  = (const float*)d_in[1];
    const float* b_att  = (const float*)d_in[2];
    const float* w_proj = (const float*)d_in[3];
    const float* b_proj = (const float*)d_in[4];
    float* out = (float*)d_out;

    cudaFuncSetAttribute(mgemm5_kernel<0>,
                         cudaFuncAttributeMaxDynamicSharedMemorySize, GEMM_SMEM);
    cudaFuncSetAttribute(mgemm5_kernel<1>,
                         cudaFuncAttributeMaxDynamicSharedMemorySize, GEMM_SMEM);
    const int attn_smem = ATTN_FLOATS * (int)sizeof(float);
    cudaFuncSetAttribute(attn_kernel,
                         cudaFuncAttributeMaxDynamicSharedMemorySize, attn_smem);

    // 0) convert inputs to fp16 scratch copies
    __half* d_xh;  cudaGetSymbolAddress((void**)&d_xh,  g_xh);
    __half* d_wah; cudaGetSymbolAddress((void**)&d_wah, g_wah);
    __half* d_wph; cudaGetSymbolAddress((void**)&d_wph, g_wph);
    round_h_kernel<<<(NM*NC/4 + 255)/256, 256>>>(x, d_xh, NM*NC/4);
    round_h_kernel<<<(N3C*NC/4 + 255)/256, 256>>>(w_att, d_wah, N3C*NC/4);
    round_h_kernel<<<(NC*NC/4 + 255)/256, 256>>>(w_proj, d_wph, NC*NC/4);

    // 1) QKV projection (fp16 mma, 2 CTAs/SM) -> q/k/v (fp32)
    dim3 g1(N3C / 128, NM / 128);   // (48, 32)
    mgemm5_kernel<0><<<g1, 256, GEMM_SMEM>>>(b_att, nullptr);

    // 2) RoPE in-place on q, k
    rope_kernel<<<(2 * NB * NH * NT * (HD/2)) / 256, 256>>>();

    // 3) causal flash attention (tf32 mma) -> g_yh [B,T,C] fp16
    attn_kernel<<<dim3(NT / 128, NB * NH), 256, attn_smem>>>();

    // 4) output projection (fp16 mma) -> d_out
    dim3 g2(NC / 128, NM / 128);    // (16, 32)
    mgemm5_kernel<1><<<g2, 256, GEMM_SMEM>>>(b_proj, out);
}